// round 9
// baseline (speedup 1.0000x reference)
#include <cuda_runtime.h>
#include <cstdint>
#include <math.h>

#define BSZ   8192
#define IND   1024
#define OUTD  1024
#define NSPLIT 4
#define NCHUNK 512

// ---- scratch (static device globals; no dynamic allocation) ----
__device__ float    g_u  [(size_t)BSZ * OUTD];           // 32 MB
__device__ float    g_yn [(size_t)BSZ * OUTD];           // 32 MB
__device__ float    g_P  [NCHUNK * OUTD];
__device__ float    g_m  [OUTD];
__device__ float    g_rate[OUTD];
__device__ float    g_S  [(size_t)NSPLIT * OUTD * IND];  // 16 MB
// pre-split bf16 operands
__device__ uint16_t g_xh [(size_t)BSZ * IND];
__device__ uint16_t g_xl [(size_t)BSZ * IND];
__device__ uint16_t g_Wh [(size_t)OUTD * IND];
__device__ uint16_t g_Wl [(size_t)OUTD * IND];
__device__ uint16_t g_xTh[(size_t)IND * BSZ];
__device__ uint16_t g_xTl[(size_t)IND * BSZ];
__device__ uint16_t g_ynTh[(size_t)OUTD * BSZ];
__device__ uint16_t g_ynTl[(size_t)OUTD * BSZ];

// ============================================================
// helpers
// ============================================================
__device__ __forceinline__ uint32_t bf16x2_rn(float hi, float lo) {
    uint32_t r;
    asm("cvt.rn.bf16x2.f32 %0, %1, %2;" : "=r"(r) : "f"(hi), "f"(lo));
    return r;
}
__device__ __forceinline__ void mma_bf16_k16(float c[4], const uint32_t a[4],
                                             const uint32_t b[2])
{
    asm volatile(
        "mma.sync.aligned.m16n8k16.row.col.f32.bf16.bf16.f32 "
        "{%0,%1,%2,%3}, {%4,%5,%6,%7}, {%8,%9}, {%0,%1,%2,%3};\n"
        : "+f"(c[0]), "+f"(c[1]), "+f"(c[2]), "+f"(c[3])
        : "r"(a[0]), "r"(a[1]), "r"(a[2]), "r"(a[3]),
          "r"(b[0]), "r"(b[1]));
}
__device__ __forceinline__ void ldsm_x4(uint32_t r[4], uint32_t addr) {
    asm volatile("ldmatrix.sync.aligned.m8n8.x4.shared.b16 {%0,%1,%2,%3}, [%4];"
        : "=r"(r[0]), "=r"(r[1]), "=r"(r[2]), "=r"(r[3]) : "r"(addr));
}
#define CP_ASYNC16(saddr, gptr) \
    asm volatile("cp.async.cg.shared.global [%0], [%1], 16;" \
        :: "r"(saddr), "l"(gptr))
#define CP_COMMIT()  asm volatile("cp.async.commit_group;")
#define CP_WAIT(n)   asm volatile("cp.async.wait_group %0;" :: "n"(n))

// Stage geometry: K=32 bf16, A = 256 rows (M), B = 128 rows (N), stride 40
#define BK      32
#define BM      256
#define BN      128
#define STRIDE  40
#define SM_AH   0
#define SM_AL   (BM * STRIDE * 2)                          // 20480
#define SM_BH   (2 * BM * STRIDE * 2)                      // 40960
#define SM_BL   (2 * BM * STRIDE * 2 + BN * STRIDE * 2)    // 51200
#define STAGE_B (2 * BM * STRIDE * 2 + 2 * BN * STRIDE * 2) // 61440
#define NSTAGE  3
#define SMEM_BYTES (NSTAGE * STAGE_B)                      // 184320

__device__ __forceinline__ void fill_stage(
    uint32_t sbase, int t,
    const uint16_t* __restrict__ Ah, const uint16_t* __restrict__ Al, int lda,
    const uint16_t* __restrict__ Bh, const uint16_t* __restrict__ Bl, int ldb,
    int m0, int n0, int ks0)
{
    // A: 256 rows x 4 16B-chunks = 1024 chunks per buffer (256 thr x 4)
#pragma unroll
    for (int i = 0; i < 4; ++i) {
        const int c   = t + 256 * i;
        const int row = c >> 2;
        const int c16 = c & 3;
        const size_t go = (size_t)(m0 + row) * lda + ks0 + c16 * 8;
        const uint32_t so = (uint32_t)((row * STRIDE + c16 * 8) * 2);
        CP_ASYNC16(sbase + SM_AH + so, Ah + go);
        CP_ASYNC16(sbase + SM_AL + so, Al + go);
    }
    // B: 128 rows x 4 chunks = 512 per buffer (256 thr x 2)
#pragma unroll
    for (int i = 0; i < 2; ++i) {
        const int c   = t + 256 * i;
        const int row = c >> 2;
        const int c16 = c & 3;
        const size_t go = (size_t)(n0 + row) * ldb + ks0 + c16 * 8;
        const uint32_t so = (uint32_t)((row * STRIDE + c16 * 8) * 2);
        CP_ASYNC16(sbase + SM_BH + so, Bh + go);
        CP_ASYNC16(sbase + SM_BL + so, Bl + go);
    }
}

// ============================================================
// bf16x3 pipelined mma.sync GEMM, warp tile 64x64.
// D[m0+r][n0+c] = sum_k A[m][k]*B[n][k] (+bias[n]); A,B pre-split bf16 K-major.
// CTA 256x128, 256 thr / 8 warps (4M x 2N), 3-stage cp.async ring.
// ============================================================
__global__ __launch_bounds__(256, 1) void gemm_bf16v4_kernel(
    const uint16_t* __restrict__ Ah, const uint16_t* __restrict__ Al, int lda,
    const uint16_t* __restrict__ Bh, const uint16_t* __restrict__ Bl, int ldb,
    int kzstep, float* __restrict__ dstBase, int ldd, size_t zstride,
    const float* __restrict__ bias, int nstages)
{
    extern __shared__ uint16_t sm[];
    const uint32_t sbase0 = (uint32_t)__cvta_generic_to_shared(sm);

    const int t     = threadIdx.x;
    const int lane  = t & 31;
    const int warp  = t >> 5;
    const int warpM = warp & 3;    // 0..3 -> 64-row slab
    const int warpN = warp >> 2;   // 0..1 -> 64-col slab
    const int m0    = blockIdx.y * BM;
    const int n0    = blockIdx.x * BN;
    const int kbase = blockIdx.z * kzstep;
    float* dst = dstBase + (size_t)blockIdx.z * zstride;

    const int gr   = lane >> 2;
    const int la15 = lane & 15;
    const int lhi  = lane >> 4;

    uint32_t aoff[4], boff[4];
#pragma unroll
    for (int mt = 0; mt < 4; ++mt)
        aoff[mt] = (uint32_t)(((warpM * 64 + mt * 16 + la15) * STRIDE
                               + lhi * 8) * 2);
#pragma unroll
    for (int p = 0; p < 4; ++p)
        boff[p] = (uint32_t)(((warpN * 64 + p * 16 + lhi * 8 + (lane & 7))
                               * STRIDE + ((lane >> 3) & 1) * 8) * 2);

    float c[4][8][4];
#pragma unroll
    for (int mt = 0; mt < 4; ++mt)
#pragma unroll
        for (int nt = 0; nt < 8; ++nt)
#pragma unroll
            for (int e = 0; e < 4; ++e) c[mt][nt][e] = 0.f;

    // prologue: fill stages 0 and 1
    fill_stage(sbase0, t, Ah, Al, lda, Bh, Bl, ldb, m0, n0, kbase);
    CP_COMMIT();
    fill_stage(sbase0 + STAGE_B, t, Ah, Al, lda, Bh, Bl, ldb, m0, n0,
               kbase + BK);
    CP_COMMIT();

    int slot = 0;
    for (int s = 0; s < nstages; ++s) {
        CP_WAIT(1);          // fill(s) complete (fill(s+1) may be in flight)
        __syncthreads();     // all warps done consuming slot (s+2)%3
        if (s + 2 < nstages) {
            fill_stage(sbase0 + ((slot + 2) % NSTAGE) * STAGE_B, t,
                       Ah, Al, lda, Bh, Bl, ldb, m0, n0,
                       kbase + (s + 2) * BK);
        }
        CP_COMMIT();         // unconditional: keeps group counting correct

        const uint32_t sb  = sbase0 + slot * STAGE_B;
        const uint32_t sAh = sb + SM_AH;
        const uint32_t sAl = sb + SM_AL;
        const uint32_t sBh = sb + SM_BH;
        const uint32_t sBl = sb + SM_BL;
        slot = (slot + 1) % NSTAGE;

#pragma unroll
        for (int ks = 0; ks < 2; ++ks) {
            const uint32_t ko = (uint32_t)(ks * 32);
            uint32_t ah[4][4], al[4][4], bh[8][2], bl[8][2], t4[4];

            // hoist ALL fragment loads for this ks
#pragma unroll
            for (int mt = 0; mt < 4; ++mt)
                ldsm_x4(ah[mt], sAh + aoff[mt] + ko);
#pragma unroll
            for (int p = 0; p < 4; ++p) {
                ldsm_x4(t4, sBh + boff[p] + ko);
                bh[2*p][0] = t4[0]; bh[2*p][1] = t4[1];
                bh[2*p+1][0] = t4[2]; bh[2*p+1][1] = t4[3];
            }
#pragma unroll
            for (int p = 0; p < 4; ++p) {
                ldsm_x4(t4, sBl + boff[p] + ko);
                bl[2*p][0] = t4[0]; bl[2*p][1] = t4[1];
                bl[2*p+1][0] = t4[2]; bl[2*p+1][1] = t4[3];
            }
#pragma unroll
            for (int mt = 0; mt < 4; ++mt)
                ldsm_x4(al[mt], sAl + aoff[mt] + ko);

            // hi*hi
#pragma unroll
            for (int mt = 0; mt < 4; ++mt)
#pragma unroll
                for (int nt = 0; nt < 8; ++nt)
                    mma_bf16_k16(c[mt][nt], ah[mt], bh[nt]);
            // hi*lo
#pragma unroll
            for (int mt = 0; mt < 4; ++mt)
#pragma unroll
                for (int nt = 0; nt < 8; ++nt)
                    mma_bf16_k16(c[mt][nt], ah[mt], bl[nt]);
            // lo*hi
#pragma unroll
            for (int mt = 0; mt < 4; ++mt)
#pragma unroll
                for (int nt = 0; nt < 8; ++nt)
                    mma_bf16_k16(c[mt][nt], al[mt], bh[nt]);
        }
    }

    // ---- epilogue ----
#pragma unroll
    for (int mt = 0; mt < 4; ++mt) {
        const int r = m0 + warpM * 64 + mt * 16 + gr;
#pragma unroll
        for (int nt = 0; nt < 8; ++nt) {
            const int cc = n0 + warpN * 64 + nt * 8 + (lane & 3) * 2;
            float2 v0 = make_float2(c[mt][nt][0], c[mt][nt][1]);
            float2 v1 = make_float2(c[mt][nt][2], c[mt][nt][3]);
            if (bias) {
                const float b0 = __ldg(&bias[cc]);
                const float b1 = __ldg(&bias[cc + 1]);
                v0.x += b0; v0.y += b1;
                v1.x += b0; v1.y += b1;
            }
            *reinterpret_cast<float2*>(&dst[(size_t)r * ldd + cc])       = v0;
            *reinterpret_cast<float2*>(&dst[(size_t)(r + 8) * ldd + cc]) = v1;
        }
    }
}

// ============================================================
// Elementwise split: v -> hi = trunc-bf16(v), lo = rn-bf16(v - hi)
// ============================================================
__global__ __launch_bounds__(256) void split_kernel(
    const float* __restrict__ src, uint16_t* __restrict__ dh,
    uint16_t* __restrict__ dl, int n4)
{
    const int i = blockIdx.x * 256 + threadIdx.x;
    if (i >= n4) return;
    float4 v = reinterpret_cast<const float4*>(src)[i];
    uint32_t x0 = __float_as_uint(v.x), x1 = __float_as_uint(v.y);
    uint32_t x2 = __float_as_uint(v.z), x3 = __float_as_uint(v.w);
    uint32_t h01 = __byte_perm(x0, x1, 0x7632);
    uint32_t h23 = __byte_perm(x2, x3, 0x7632);
    float l0 = v.x - __uint_as_float(x0 & 0xFFFF0000u);
    float l1 = v.y - __uint_as_float(x1 & 0xFFFF0000u);
    float l2 = v.z - __uint_as_float(x2 & 0xFFFF0000u);
    float l3 = v.w - __uint_as_float(x3 & 0xFFFF0000u);
    reinterpret_cast<uint2*>(dh)[i] = make_uint2(h01, h23);
    reinterpret_cast<uint2*>(dl)[i] =
        make_uint2(bf16x2_rn(l1, l0), bf16x2_rn(l3, l2));
}

// ============================================================
// Transpose + split: src fp32 [R][C] -> dsthi/dstlo bf16 [C][R]
// ============================================================
__global__ __launch_bounds__(256) void transpose_split_kernel(
    const float* __restrict__ src, uint16_t* __restrict__ dh,
    uint16_t* __restrict__ dl, int R, int C)
{
    __shared__ float tile[32][33];
    const int c0 = blockIdx.x * 32;
    const int r0 = blockIdx.y * 32;
    const int tx = threadIdx.x, ty = threadIdx.y;
#pragma unroll
    for (int i = 0; i < 4; ++i)
        tile[ty + i*8][tx] = src[(size_t)(r0 + ty + i*8) * C + c0 + tx];
    __syncthreads();
#pragma unroll
    for (int i = 0; i < 4; ++i) {
        float v = tile[tx][ty + i*8];
        uint32_t u = __float_as_uint(v);
        uint16_t hi = (uint16_t)(u >> 16);
        float lo = v - __uint_as_float(u & 0xFFFF0000u);
        uint32_t lop = bf16x2_rn(lo, lo);
        const size_t o = (size_t)(c0 + ty + i*8) * R + r0 + tx;
        dh[o] = hi;
        dl[o] = (uint16_t)(lop & 0xFFFF);
    }
}

// ============================================================
// Per-row softmax + negate-non-maximal
// ============================================================
__global__ __launch_bounds__(256) void softmax_neg_kernel()
{
    const int b = blockIdx.x;
    const int t = threadIdx.x;
    const unsigned full = 0xffffffffu;

    float4 v = reinterpret_cast<const float4*>(&g_u[(size_t)b * OUTD])[t];

    float mx = v.x; int ai = t*4;
    if (v.y > mx) { mx = v.y; ai = t*4+1; }
    if (v.z > mx) { mx = v.z; ai = t*4+2; }
    if (v.w > mx) { mx = v.w; ai = t*4+3; }

#pragma unroll
    for (int off = 16; off > 0; off >>= 1) {
        float omx = __shfl_down_sync(full, mx, off);
        int   oai = __shfl_down_sync(full, ai, off);
        if (omx > mx || (omx == mx && oai < ai)) { mx = omx; ai = oai; }
    }
    __shared__ float smx[8];
    __shared__ int   sai[8];
    __shared__ float ssum[8];
    const int warp = t >> 5, lane = t & 31;
    if (lane == 0) { smx[warp] = mx; sai[warp] = ai; }
    __syncthreads();
    if (t == 0) {
        for (int w = 1; w < 8; ++w)
            if (smx[w] > smx[0] || (smx[w] == smx[0] && sai[w] < sai[0])) {
                smx[0] = smx[w]; sai[0] = sai[w];
            }
    }
    __syncthreads();
    const float MX = smx[0];
    const int   AI = sai[0];

    float4 e;
    e.x = expf(v.x - MX); e.y = expf(v.y - MX);
    e.z = expf(v.z - MX); e.w = expf(v.w - MX);
    float s = e.x + e.y + e.z + e.w;
#pragma unroll
    for (int off = 16; off > 0; off >>= 1) s += __shfl_down_sync(full, s, off);
    if (lane == 0) ssum[warp] = s;
    __syncthreads();
    if (t == 0) {
        float tot = 0.f;
        for (int w = 0; w < 8; ++w) tot += ssum[w];
        ssum[0] = tot;
    }
    __syncthreads();
    const float inv = 1.f / ssum[0];

    float4 o;
    o.x = (t*4+0 == AI) ? e.x*inv : -e.x*inv;
    o.y = (t*4+1 == AI) ? e.y*inv : -e.y*inv;
    o.z = (t*4+2 == AI) ? e.z*inv : -e.z*inv;
    o.w = (t*4+3 == AI) ? e.w*inv : -e.w*inv;
    reinterpret_cast<float4*>(&g_yn[(size_t)b * OUTD])[t] = o;
}

// ============================================================
// rate[o] = 1e-3 * |1 - ||W[o,:]||_2|^0.5
// ============================================================
__global__ __launch_bounds__(256) void rate_kernel(const float* __restrict__ W)
{
    const int o = blockIdx.x;
    const int t = threadIdx.x;
    const unsigned full = 0xffffffffu;
    float4 w = reinterpret_cast<const float4*>(&W[(size_t)o * IND])[t];
    float s = w.x*w.x + w.y*w.y + w.z*w.z + w.w*w.w;
#pragma unroll
    for (int off = 16; off > 0; off >>= 1) s += __shfl_down_sync(full, s, off);
    __shared__ float ssum[8];
    const int warp = t >> 5, lane = t & 31;
    if (lane == 0) ssum[warp] = s;
    __syncthreads();
    if (t == 0) {
        float tot = 0.f;
        for (int w2 = 0; w2 < 8; ++w2) tot += ssum[w2];
        float norm = sqrtf(tot);
        g_rate[o] = 1e-3f * sqrtf(fabsf(1.f - norm));
    }
}

// ============================================================
// m[o] = mean_b(yn[b,o] * u[b,o])
// ============================================================
__global__ __launch_bounds__(256) void col_partial_kernel()
{
    const int o = blockIdx.x * 256 + threadIdx.x;
    const int c = blockIdx.y;
    const int r0 = c * (BSZ / NCHUNK);
    float acc = 0.f;
#pragma unroll
    for (int r = 0; r < BSZ / NCHUNK; ++r) {
        const size_t off = (size_t)(r0 + r) * OUTD + o;
        acc += g_yn[off] * g_u[off];
    }
    g_P[c * OUTD + o] = acc;
}

__global__ __launch_bounds__(256) void m_final_kernel()
{
    const int o = blockIdx.x * 256 + threadIdx.x;
    float acc = 0.f;
    for (int c = 0; c < NCHUNK; ++c) acc += g_P[c * OUTD + o];
    g_m[o] = acc * (1.f / (float)BSZ);
}

// ============================================================
// out[o,i] = rate[o] * (sum_s S[s][o,i]/B - m[o]*W[o,i])
// ============================================================
__global__ __launch_bounds__(256) void epilogue_kernel(
    const float* __restrict__ W, float* __restrict__ out)
{
    const int o = blockIdx.x;
    const int t = threadIdx.x;
    const float m = g_m[o];
    const float r = g_rate[o];
    float4 wv = reinterpret_cast<const float4*>(&W[(size_t)o * IND])[t];
    float4 s = make_float4(0.f, 0.f, 0.f, 0.f);
#pragma unroll
    for (int sp = 0; sp < NSPLIT; ++sp) {
        float4 p = reinterpret_cast<const float4*>(
            &g_S[(size_t)sp * OUTD * IND + (size_t)o * IND])[t];
        s.x += p.x; s.y += p.y; s.z += p.z; s.w += p.w;
    }
    const float invB = 1.f / (float)BSZ;
    float4 ov;
    ov.x = r * (s.x * invB - m * wv.x);
    ov.y = r * (s.y * invB - m * wv.y);
    ov.z = r * (s.z * invB - m * wv.z);
    ov.w = r * (s.w * invB - m * wv.w);
    reinterpret_cast<float4*>(&out[(size_t)o * IND])[t] = ov;
}

// ============================================================
extern "C" void kernel_launch(void* const* d_in, const int* in_sizes, int n_in,
                              void* d_out, int out_size)
{
    const float* x = (const float*)d_in[0];   // [8192, 1024]
    const float* W = (const float*)d_in[1];   // [1024, 1024]
    const float* b = (const float*)d_in[2];   // [1024]
    float* out = (float*)d_out;               // [1024, 1024]

    cudaFuncSetAttribute(gemm_bf16v4_kernel,
                         cudaFuncAttributeMaxDynamicSharedMemorySize, SMEM_BYTES);

    float*    g_u_p;    cudaGetSymbolAddress((void**)&g_u_p,    g_u);
    float*    g_yn_p;   cudaGetSymbolAddress((void**)&g_yn_p,   g_yn);
    float*    g_S_p;    cudaGetSymbolAddress((void**)&g_S_p,    g_S);
    uint16_t* g_xh_p;   cudaGetSymbolAddress((void**)&g_xh_p,   g_xh);
    uint16_t* g_xl_p;   cudaGetSymbolAddress((void**)&g_xl_p,   g_xl);
    uint16_t* g_Wh_p;   cudaGetSymbolAddress((void**)&g_Wh_p,   g_Wh);
    uint16_t* g_Wl_p;   cudaGetSymbolAddress((void**)&g_Wl_p,   g_Wl);
    uint16_t* g_xTh_p;  cudaGetSymbolAddress((void**)&g_xTh_p,  g_xTh);
    uint16_t* g_xTl_p;  cudaGetSymbolAddress((void**)&g_xTl_p,  g_xTl);
    uint16_t* g_ynTh_p; cudaGetSymbolAddress((void**)&g_ynTh_p, g_ynTh);
    uint16_t* g_ynTl_p; cudaGetSymbolAddress((void**)&g_ynTl_p, g_ynTl);

    // split inputs to bf16 hi/lo (once)
    split_kernel<<<(BSZ*IND/4 + 255)/256, 256>>>(x, g_xh_p, g_xl_p, BSZ*IND/4);
    split_kernel<<<(OUTD*IND/4 + 255)/256, 256>>>(W, g_Wh_p, g_Wl_p, OUTD*IND/4);
    transpose_split_kernel<<<dim3(IND/32, BSZ/32), dim3(32, 8)>>>(
        x, g_xTh_p, g_xTl_p, BSZ, IND);

    // u = x @ W^T + b
    gemm_bf16v4_kernel<<<dim3(OUTD/BN, BSZ/BM, 1), 256, SMEM_BYTES>>>(
        g_xh_p, g_xl_p, IND, g_Wh_p, g_Wl_p, IND,
        0, g_u_p, OUTD, 0, b, IND / BK);
    // yn = negate_non_maximal(softmax(u))
    softmax_neg_kernel<<<BSZ, 256>>>();
    // yn^T split
    transpose_split_kernel<<<dim3(OUTD/32, BSZ/32), dim3(32, 8)>>>(
        g_yn_p, g_ynTh_p, g_ynTl_p, BSZ, OUTD);
    // per-row rate + m[o]
    rate_kernel<<<OUTD, 256>>>(W);
    col_partial_kernel<<<dim3(OUTD/256, NCHUNK), 256>>>();
    m_final_kernel<<<OUTD/256, 256>>>();
    // S[z] = yn^T @ x partials (split-K = 4, single wave of 128 CTAs)
    gemm_bf16v4_kernel<<<dim3(IND/BN, OUTD/BM, NSPLIT), 256, SMEM_BYTES>>>(
        g_ynTh_p, g_ynTl_p, BSZ, g_xTh_p, g_xTl_p, BSZ,
        BSZ/NSPLIT, g_S_p, IND, (size_t)OUTD * IND, nullptr,
        (BSZ/NSPLIT) / BK);
    // out = rate * (sum S / B - m*W)
    epilogue_kernel<<<OUTD, 256>>>(W, out);
}

// round 11
// speedup vs baseline: 1.1875x; 1.1875x over previous
#include <cuda_runtime.h>
#include <cstdint>
#include <math.h>

#define BSZ   8192
#define IND   1024
#define OUTD  1024
#define NSPLIT 4
#define NCHUNK 512

// ---- scratch (static device globals; no dynamic allocation) ----
__device__ float    g_u  [(size_t)BSZ * OUTD];           // 32 MB
__device__ float    g_yn [(size_t)BSZ * OUTD];           // 32 MB
__device__ float    g_P  [NCHUNK * OUTD];
__device__ float    g_m  [OUTD];
__device__ float    g_rate[OUTD];
__device__ float    g_S  [(size_t)NSPLIT * OUTD * IND];  // 16 MB
// pre-split bf16 operands
__device__ uint16_t g_xh [(size_t)BSZ * IND];
__device__ uint16_t g_xl [(size_t)BSZ * IND];
__device__ uint16_t g_Wh [(size_t)OUTD * IND];
__device__ uint16_t g_Wl [(size_t)OUTD * IND];
__device__ uint16_t g_xTh[(size_t)IND * BSZ];
__device__ uint16_t g_xTl[(size_t)IND * BSZ];
__device__ uint16_t g_ynTh[(size_t)OUTD * BSZ];
__device__ uint16_t g_ynTl[(size_t)OUTD * BSZ];

// ============================================================
// helpers
// ============================================================
__device__ __forceinline__ uint32_t bf16x2_rn(float hi, float lo) {
    uint32_t r;
    asm("cvt.rn.bf16x2.f32 %0, %1, %2;" : "=r"(r) : "f"(hi), "f"(lo));
    return r;
}
__device__ __forceinline__ void mma_bf16_k16(float c[4], const uint32_t a[4],
                                             const uint32_t b[2])
{
    asm volatile(
        "mma.sync.aligned.m16n8k16.row.col.f32.bf16.bf16.f32 "
        "{%0,%1,%2,%3}, {%4,%5,%6,%7}, {%8,%9}, {%0,%1,%2,%3};\n"
        : "+f"(c[0]), "+f"(c[1]), "+f"(c[2]), "+f"(c[3])
        : "r"(a[0]), "r"(a[1]), "r"(a[2]), "r"(a[3]),
          "r"(b[0]), "r"(b[1]));
}
__device__ __forceinline__ void ldsm_x4(uint32_t r[4], uint32_t addr) {
    asm volatile("ldmatrix.sync.aligned.m8n8.x4.shared.b16 {%0,%1,%2,%3}, [%4];"
        : "=r"(r[0]), "=r"(r[1]), "=r"(r[2]), "=r"(r[3]) : "r"(addr));
}
#define CP_ASYNC16(saddr, gptr) \
    asm volatile("cp.async.cg.shared.global [%0], [%1], 16;" \
        :: "r"(saddr), "l"(gptr))
// NOTE .noinc: arrive WITHOUT bumping expected-count (barrier inited to NTHREADS).
// The default (inc) form nets zero against the phase -> R10 deadlock.
#define CP_MBAR_ARRIVE(mbar) \
    asm volatile("cp.async.mbarrier.arrive.noinc.shared::cta.b64 [%0];" \
        :: "r"((uint32_t)(mbar)) : "memory")
#define MBARRIER_INIT(mbar, cnt) \
    asm volatile("mbarrier.init.shared.b64 [%0], %1;" \
        :: "r"((uint32_t)(mbar)), "r"((uint32_t)(cnt)) : "memory")
#define MBARRIER_ARRIVE(mbar) \
    asm volatile("mbarrier.arrive.shared::cta.b64 _, [%0];" \
        :: "r"((uint32_t)(mbar)) : "memory")
#define MBARRIER_WAIT_PARITY(mbar, parity) do {                                   \
    uint32_t _m = (uint32_t)(mbar); uint32_t _p = (uint32_t)(parity);             \
    uint32_t _done;                                                               \
    asm volatile("{\n\t.reg .pred p;\n\t"                                         \
        "mbarrier.try_wait.parity.acquire.cta.shared::cta.b64 p, [%1], %2;\n\t"   \
        "selp.b32 %0, 1, 0, p;\n\t}" : "=r"(_done) : "r"(_m), "r"(_p) : "memory");\
    if (!_done) {                                                                 \
        asm volatile("{\n\t.reg .pred P1;\n\t"                                    \
            "WL_%=:\n\t"                                                          \
            "mbarrier.try_wait.parity.acquire.cta.shared::cta.b64 P1, [%0], %1, 0x989680;\n\t" \
            "@P1 bra.uni WD_%=;\n\t"                                              \
            "bra.uni WL_%=;\n\t"                                                  \
            "WD_%=:\n\t}" :: "r"(_m), "r"(_p) : "memory");                        \
    }                                                                             \
} while (0)

// Stage geometry: K=32 bf16, A = 256 rows (M), B = 128 rows (N), stride 40
#define BK      32
#define BM      256
#define BN      128
#define STRIDE  40
#define SM_AH   0
#define SM_AL   (BM * STRIDE * 2)                          // 20480
#define SM_BH   (2 * BM * STRIDE * 2)                      // 40960
#define SM_BL   (2 * BM * STRIDE * 2 + BN * STRIDE * 2)    // 51200
#define STAGE_B (2 * BM * STRIDE * 2 + 2 * BN * STRIDE * 2) // 61440
#define NSTAGE  3
#define SM_BARS (NSTAGE * STAGE_B)                         // 184320
#define SMEM_BYTES (SM_BARS + 64)                          // + mbarriers
#define NTHREADS 512

__device__ __forceinline__ void fill_stage(
    uint32_t sbase, int t,
    const uint16_t* __restrict__ Ah, const uint16_t* __restrict__ Al, int lda,
    const uint16_t* __restrict__ Bh, const uint16_t* __restrict__ Bl, int ldb,
    int m0, int n0, int ks0)
{
    // A: 256 rows x 4 16B-chunks = 1024 chunks (512 thr x 2)
#pragma unroll
    for (int i = 0; i < 2; ++i) {
        const int c   = t + 512 * i;
        const int row = c >> 2;
        const int c16 = c & 3;
        const size_t go = (size_t)(m0 + row) * lda + ks0 + c16 * 8;
        const uint32_t so = (uint32_t)((row * STRIDE + c16 * 8) * 2);
        CP_ASYNC16(sbase + SM_AH + so, Ah + go);
        CP_ASYNC16(sbase + SM_AL + so, Al + go);
    }
    // B: 128 rows x 4 chunks = 512 (512 thr x 1)
    {
        const int row = t >> 2;
        const int c16 = t & 3;
        const size_t go = (size_t)(n0 + row) * ldb + ks0 + c16 * 8;
        const uint32_t so = (uint32_t)((row * STRIDE + c16 * 8) * 2);
        CP_ASYNC16(sbase + SM_BH + so, Bh + go);
        CP_ASYNC16(sbase + SM_BL + so, Bl + go);
    }
}

// ============================================================
// bf16x3 mma.sync GEMM with mbarrier full/empty ring (de-phased warps).
// D[m0+r][n0+c] = sum_k A[m][k]*B[n][k] (+bias[n]); A,B pre-split bf16 K-major.
// CTA 256x128, 512 thr / 16 warps (4M x 4N), warp tile 64x32.
// 3-slot ring, prefetch depth 1, NO __syncthreads in the mainloop.
// ============================================================
__global__ __launch_bounds__(NTHREADS, 1) void gemm_bf16v5_kernel(
    const uint16_t* __restrict__ Ah, const uint16_t* __restrict__ Al, int lda,
    const uint16_t* __restrict__ Bh, const uint16_t* __restrict__ Bl, int ldb,
    int kzstep, float* __restrict__ dstBase, int ldd, size_t zstride,
    const float* __restrict__ bias, int nstages)
{
    extern __shared__ uint16_t sm[];
    const uint32_t sbase0 = (uint32_t)__cvta_generic_to_shared(sm);
    const uint32_t barF = sbase0 + SM_BARS;        // full[0..2], 8 B each
    const uint32_t barE = sbase0 + SM_BARS + 24;   // empty[0..2]

    const int t     = threadIdx.x;
    const int lane  = t & 31;
    const int warp  = t >> 5;
    const int warpM = warp & 3;    // 0..3
    const int warpN = warp >> 2;   // 0..3
    const int m0    = blockIdx.y * BM;
    const int n0    = blockIdx.x * BN;
    const int kbase = blockIdx.z * kzstep;
    float* dst = dstBase + (size_t)blockIdx.z * zstride;

    const int gr   = lane >> 2;
    const int la15 = lane & 15;
    const int lhi  = lane >> 4;

    uint32_t aoff[4], boff[2];
#pragma unroll
    for (int mt = 0; mt < 4; ++mt)
        aoff[mt] = (uint32_t)(((warpM * 64 + mt * 16 + la15) * STRIDE
                               + lhi * 8) * 2);
#pragma unroll
    for (int p = 0; p < 2; ++p)
        boff[p] = (uint32_t)(((warpN * 32 + p * 16 + lhi * 8 + (lane & 7))
                               * STRIDE + ((lane >> 3) & 1) * 8) * 2);

    if (t == 0) {
#pragma unroll
        for (int j = 0; j < NSTAGE; ++j) {
            MBARRIER_INIT(barF + j * 8, NTHREADS);
            MBARRIER_INIT(barE + j * 8, NTHREADS);
        }
    }
    __syncthreads();   // barriers initialized before any arrive

    float c[4][4][4];
#pragma unroll
    for (int mt = 0; mt < 4; ++mt)
#pragma unroll
        for (int nt = 0; nt < 4; ++nt)
#pragma unroll
            for (int e = 0; e < 4; ++e) c[mt][nt][e] = 0.f;

    // prologue: fill stage 0 into slot 0
    fill_stage(sbase0, t, Ah, Al, lda, Bh, Bl, ldb, m0, n0, kbase);
    CP_MBAR_ARRIVE(barF);

    int fs = 1, pslot = 1, pph = 0;   // producer cursor (next stage to fill)
    int cslot = 0, cph = 0;           // consumer cursor

    for (int s = 0; s < nstages; ++s) {
        // ---- prefetch stage fs (depth 1) ----
        if (fs < nstages) {
            if (fs >= NSTAGE)
                MBARRIER_WAIT_PARITY(barE + pslot * 8, pph ^ 1);
            fill_stage(sbase0 + pslot * STAGE_B, t, Ah, Al, lda, Bh, Bl, ldb,
                       m0, n0, kbase + fs * BK);
            CP_MBAR_ARRIVE(barF + pslot * 8);
            ++fs;
            if (++pslot == NSTAGE) { pslot = 0; pph ^= 1; }
        }

        // ---- consume stage s ----
        MBARRIER_WAIT_PARITY(barF + cslot * 8, cph);
        const uint32_t sb  = sbase0 + cslot * STAGE_B;
        const uint32_t sAh = sb + SM_AH;
        const uint32_t sAl = sb + SM_AL;
        const uint32_t sBh = sb + SM_BH;
        const uint32_t sBl = sb + SM_BL;

#pragma unroll
        for (int ks = 0; ks < 2; ++ks) {
            const uint32_t ko = (uint32_t)(ks * 32);
            uint32_t ah[4][4], bb[4][2], t4[4];

#pragma unroll
            for (int mt = 0; mt < 4; ++mt)
                ldsm_x4(ah[mt], sAh + aoff[mt] + ko);
#pragma unroll
            for (int p = 0; p < 2; ++p) {
                ldsm_x4(t4, sBh + boff[p] + ko);
                bb[2*p][0] = t4[0]; bb[2*p][1] = t4[1];
                bb[2*p+1][0] = t4[2]; bb[2*p+1][1] = t4[3];
            }
            // hi*hi
#pragma unroll
            for (int mt = 0; mt < 4; ++mt)
#pragma unroll
                for (int nt = 0; nt < 4; ++nt)
                    mma_bf16_k16(c[mt][nt], ah[mt], bb[nt]);
            // hi*lo
            {
                uint32_t bl[4][2];
#pragma unroll
                for (int p = 0; p < 2; ++p) {
                    ldsm_x4(t4, sBl + boff[p] + ko);
                    bl[2*p][0] = t4[0]; bl[2*p][1] = t4[1];
                    bl[2*p+1][0] = t4[2]; bl[2*p+1][1] = t4[3];
                }
#pragma unroll
                for (int mt = 0; mt < 4; ++mt)
#pragma unroll
                    for (int nt = 0; nt < 4; ++nt)
                        mma_bf16_k16(c[mt][nt], ah[mt], bl[nt]);
            }
            // lo*hi
            {
                uint32_t al[4][4];
#pragma unroll
                for (int mt = 0; mt < 4; ++mt)
                    ldsm_x4(al[mt], sAl + aoff[mt] + ko);
                if (ks == 1)   // last smem reads of this slot done -> free it
                    MBARRIER_ARRIVE(barE + cslot * 8);
#pragma unroll
                for (int mt = 0; mt < 4; ++mt)
#pragma unroll
                    for (int nt = 0; nt < 4; ++nt)
                        mma_bf16_k16(c[mt][nt], al[mt], bb[nt]);
            }
        }
        if (++cslot == NSTAGE) { cslot = 0; cph ^= 1; }
    }

    // ---- epilogue ----
#pragma unroll
    for (int mt = 0; mt < 4; ++mt) {
        const int r = m0 + warpM * 64 + mt * 16 + gr;
#pragma unroll
        for (int nt = 0; nt < 4; ++nt) {
            const int cc = n0 + warpN * 32 + nt * 8 + (lane & 3) * 2;
            float2 v0 = make_float2(c[mt][nt][0], c[mt][nt][1]);
            float2 v1 = make_float2(c[mt][nt][2], c[mt][nt][3]);
            if (bias) {
                const float b0 = __ldg(&bias[cc]);
                const float b1 = __ldg(&bias[cc + 1]);
                v0.x += b0; v0.y += b1;
                v1.x += b0; v1.y += b1;
            }
            *reinterpret_cast<float2*>(&dst[(size_t)r * ldd + cc])       = v0;
            *reinterpret_cast<float2*>(&dst[(size_t)(r + 8) * ldd + cc]) = v1;
        }
    }
}

// ============================================================
// Elementwise split: v -> hi = trunc-bf16(v), lo = rn-bf16(v - hi)
// ============================================================
__global__ __launch_bounds__(256) void split_kernel(
    const float* __restrict__ src, uint16_t* __restrict__ dh,
    uint16_t* __restrict__ dl, int n4)
{
    const int i = blockIdx.x * 256 + threadIdx.x;
    if (i >= n4) return;
    float4 v = reinterpret_cast<const float4*>(src)[i];
    uint32_t x0 = __float_as_uint(v.x), x1 = __float_as_uint(v.y);
    uint32_t x2 = __float_as_uint(v.z), x3 = __float_as_uint(v.w);
    uint32_t h01 = __byte_perm(x0, x1, 0x7632);
    uint32_t h23 = __byte_perm(x2, x3, 0x7632);
    float l0 = v.x - __uint_as_float(x0 & 0xFFFF0000u);
    float l1 = v.y - __uint_as_float(x1 & 0xFFFF0000u);
    float l2 = v.z - __uint_as_float(x2 & 0xFFFF0000u);
    float l3 = v.w - __uint_as_float(x3 & 0xFFFF0000u);
    reinterpret_cast<uint2*>(dh)[i] = make_uint2(h01, h23);
    reinterpret_cast<uint2*>(dl)[i] =
        make_uint2(bf16x2_rn(l1, l0), bf16x2_rn(l3, l2));
}

// ============================================================
// Transpose + split: src fp32 [R][C] -> dsthi/dstlo bf16 [C][R]
// ============================================================
__global__ __launch_bounds__(256) void transpose_split_kernel(
    const float* __restrict__ src, uint16_t* __restrict__ dh,
    uint16_t* __restrict__ dl, int R, int C)
{
    __shared__ float tile[32][33];
    const int c0 = blockIdx.x * 32;
    const int r0 = blockIdx.y * 32;
    const int tx = threadIdx.x, ty = threadIdx.y;
#pragma unroll
    for (int i = 0; i < 4; ++i)
        tile[ty + i*8][tx] = src[(size_t)(r0 + ty + i*8) * C + c0 + tx];
    __syncthreads();
#pragma unroll
    for (int i = 0; i < 4; ++i) {
        float v = tile[tx][ty + i*8];
        uint32_t u = __float_as_uint(v);
        uint16_t hi = (uint16_t)(u >> 16);
        float lo = v - __uint_as_float(u & 0xFFFF0000u);
        uint32_t lop = bf16x2_rn(lo, lo);
        const size_t o = (size_t)(c0 + ty + i*8) * R + r0 + tx;
        dh[o] = hi;
        dl[o] = (uint16_t)(lop & 0xFFFF);
    }
}

// ============================================================
// Per-row softmax + negate-non-maximal
// ============================================================
__global__ __launch_bounds__(256) void softmax_neg_kernel()
{
    const int b = blockIdx.x;
    const int t = threadIdx.x;
    const unsigned full = 0xffffffffu;

    float4 v = reinterpret_cast<const float4*>(&g_u[(size_t)b * OUTD])[t];

    float mx = v.x; int ai = t*4;
    if (v.y > mx) { mx = v.y; ai = t*4+1; }
    if (v.z > mx) { mx = v.z; ai = t*4+2; }
    if (v.w > mx) { mx = v.w; ai = t*4+3; }

#pragma unroll
    for (int off = 16; off > 0; off >>= 1) {
        float omx = __shfl_down_sync(full, mx, off);
        int   oai = __shfl_down_sync(full, ai, off);
        if (omx > mx || (omx == mx && oai < ai)) { mx = omx; ai = oai; }
    }
    __shared__ float smx[8];
    __shared__ int   sai[8];
    __shared__ float ssum[8];
    const int warp = t >> 5, lane = t & 31;
    if (lane == 0) { smx[warp] = mx; sai[warp] = ai; }
    __syncthreads();
    if (t == 0) {
        for (int w = 1; w < 8; ++w)
            if (smx[w] > smx[0] || (smx[w] == smx[0] && sai[w] < sai[0])) {
                smx[0] = smx[w]; sai[0] = sai[w];
            }
    }
    __syncthreads();
    const float MX = smx[0];
    const int   AI = sai[0];

    float4 e;
    e.x = expf(v.x - MX); e.y = expf(v.y - MX);
    e.z = expf(v.z - MX); e.w = expf(v.w - MX);
    float s = e.x + e.y + e.z + e.w;
#pragma unroll
    for (int off = 16; off > 0; off >>= 1) s += __shfl_down_sync(full, s, off);
    if (lane == 0) ssum[warp] = s;
    __syncthreads();
    if (t == 0) {
        float tot = 0.f;
        for (int w = 0; w < 8; ++w) tot += ssum[w];
        ssum[0] = tot;
    }
    __syncthreads();
    const float inv = 1.f / ssum[0];

    float4 o;
    o.x = (t*4+0 == AI) ? e.x*inv : -e.x*inv;
    o.y = (t*4+1 == AI) ? e.y*inv : -e.y*inv;
    o.z = (t*4+2 == AI) ? e.z*inv : -e.z*inv;
    o.w = (t*4+3 == AI) ? e.w*inv : -e.w*inv;
    reinterpret_cast<float4*>(&g_yn[(size_t)b * OUTD])[t] = o;
}

// ============================================================
// rate[o] = 1e-3 * |1 - ||W[o,:]||_2|^0.5
// ============================================================
__global__ __launch_bounds__(256) void rate_kernel(const float* __restrict__ W)
{
    const int o = blockIdx.x;
    const int t = threadIdx.x;
    const unsigned full = 0xffffffffu;
    float4 w = reinterpret_cast<const float4*>(&W[(size_t)o * IND])[t];
    float s = w.x*w.x + w.y*w.y + w.z*w.z + w.w*w.w;
#pragma unroll
    for (int off = 16; off > 0; off >>= 1) s += __shfl_down_sync(full, s, off);
    __shared__ float ssum[8];
    const int warp = t >> 5, lane = t & 31;
    if (lane == 0) ssum[warp] = s;
    __syncthreads();
    if (t == 0) {
        float tot = 0.f;
        for (int w2 = 0; w2 < 8; ++w2) tot += ssum[w2];
        float norm = sqrtf(tot);
        g_rate[o] = 1e-3f * sqrtf(fabsf(1.f - norm));
    }
}

// ============================================================
// m[o] = mean_b(yn[b,o] * u[b,o])
// ============================================================
__global__ __launch_bounds__(256) void col_partial_kernel()
{
    const int o = blockIdx.x * 256 + threadIdx.x;
    const int c = blockIdx.y;
    const int r0 = c * (BSZ / NCHUNK);
    float acc = 0.f;
#pragma unroll
    for (int r = 0; r < BSZ / NCHUNK; ++r) {
        const size_t off = (size_t)(r0 + r) * OUTD + o;
        acc += g_yn[off] * g_u[off];
    }
    g_P[c * OUTD + o] = acc;
}

__global__ __launch_bounds__(256) void m_final_kernel()
{
    const int o = blockIdx.x * 256 + threadIdx.x;
    float acc = 0.f;
    for (int c = 0; c < NCHUNK; ++c) acc += g_P[c * OUTD + o];
    g_m[o] = acc * (1.f / (float)BSZ);
}

// ============================================================
// out[o,i] = rate[o] * (sum_s S[s][o,i]/B - m[o]*W[o,i])
// ============================================================
__global__ __launch_bounds__(256) void epilogue_kernel(
    const float* __restrict__ W, float* __restrict__ out)
{
    const int o = blockIdx.x;
    const int t = threadIdx.x;
    const float m = g_m[o];
    const float r = g_rate[o];
    float4 wv = reinterpret_cast<const float4*>(&W[(size_t)o * IND])[t];
    float4 s = make_float4(0.f, 0.f, 0.f, 0.f);
#pragma unroll
    for (int sp = 0; sp < NSPLIT; ++sp) {
        float4 p = reinterpret_cast<const float4*>(
            &g_S[(size_t)sp * OUTD * IND + (size_t)o * IND])[t];
        s.x += p.x; s.y += p.y; s.z += p.z; s.w += p.w;
    }
    const float invB = 1.f / (float)BSZ;
    float4 ov;
    ov.x = r * (s.x * invB - m * wv.x);
    ov.y = r * (s.y * invB - m * wv.y);
    ov.z = r * (s.z * invB - m * wv.z);
    ov.w = r * (s.w * invB - m * wv.w);
    reinterpret_cast<float4*>(&out[(size_t)o * IND])[t] = ov;
}

// ============================================================
extern "C" void kernel_launch(void* const* d_in, const int* in_sizes, int n_in,
                              void* d_out, int out_size)
{
    const float* x = (const float*)d_in[0];   // [8192, 1024]
    const float* W = (const float*)d_in[1];   // [1024, 1024]
    const float* b = (const float*)d_in[2];   // [1024]
    float* out = (float*)d_out;               // [1024, 1024]

    cudaFuncSetAttribute(gemm_bf16v5_kernel,
                         cudaFuncAttributeMaxDynamicSharedMemorySize, SMEM_BYTES);

    float*    g_u_p;    cudaGetSymbolAddress((void**)&g_u_p,    g_u);
    float*    g_yn_p;   cudaGetSymbolAddress((void**)&g_yn_p,   g_yn);
    float*    g_S_p;    cudaGetSymbolAddress((void**)&g_S_p,    g_S);
    uint16_t* g_xh_p;   cudaGetSymbolAddress((void**)&g_xh_p,   g_xh);
    uint16_t* g_xl_p;   cudaGetSymbolAddress((void**)&g_xl_p,   g_xl);
    uint16_t* g_Wh_p;   cudaGetSymbolAddress((void**)&g_Wh_p,   g_Wh);
    uint16_t* g_Wl_p;   cudaGetSymbolAddress((void**)&g_Wl_p,   g_Wl);
    uint16_t* g_xTh_p;  cudaGetSymbolAddress((void**)&g_xTh_p,  g_xTh);
    uint16_t* g_xTl_p;  cudaGetSymbolAddress((void**)&g_xTl_p,  g_xTl);
    uint16_t* g_ynTh_p; cudaGetSymbolAddress((void**)&g_ynTh_p, g_ynTh);
    uint16_t* g_ynTl_p; cudaGetSymbolAddress((void**)&g_ynTl_p, g_ynTl);

    // split inputs to bf16 hi/lo (once)
    split_kernel<<<(BSZ*IND/4 + 255)/256, 256>>>(x, g_xh_p, g_xl_p, BSZ*IND/4);
    split_kernel<<<(OUTD*IND/4 + 255)/256, 256>>>(W, g_Wh_p, g_Wl_p, OUTD*IND/4);
    transpose_split_kernel<<<dim3(IND/32, BSZ/32), dim3(32, 8)>>>(
        x, g_xTh_p, g_xTl_p, BSZ, IND);

    // u = x @ W^T + b
    gemm_bf16v5_kernel<<<dim3(OUTD/BN, BSZ/BM, 1), NTHREADS, SMEM_BYTES>>>(
        g_xh_p, g_xl_p, IND, g_Wh_p, g_Wl_p, IND,
        0, g_u_p, OUTD, 0, b, IND / BK);
    // yn = negate_non_maximal(softmax(u))
    softmax_neg_kernel<<<BSZ, 256>>>();
    // yn^T split
    transpose_split_kernel<<<dim3(OUTD/32, BSZ/32), dim3(32, 8)>>>(
        g_yn_p, g_ynTh_p, g_ynTl_p, BSZ, OUTD);
    // per-row rate + m[o]
    rate_kernel<<<OUTD, 256>>>(W);
    col_partial_kernel<<<dim3(OUTD/256, NCHUNK), 256>>>();
    m_final_kernel<<<OUTD/256, 256>>>();
    // S[z] = yn^T @ x partials (split-K = 4, single wave of 128 CTAs)
    gemm_bf16v5_kernel<<<dim3(IND/BN, OUTD/BM, NSPLIT), NTHREADS, SMEM_BYTES>>>(
        g_ynTh_p, g_ynTl_p, BSZ, g_xTh_p, g_xTl_p, BSZ,
        BSZ/NSPLIT, g_S_p, IND, (size_t)OUTD * IND, nullptr,
        (BSZ/NSPLIT) / BK);
    // out = rate * (sum S / B - m*W)
    epilogue_kernel<<<OUTD, 256>>>(W, out);
}

// round 12
// speedup vs baseline: 1.3633x; 1.1481x over previous
#include <cuda_runtime.h>
#include <cuda_fp16.h>
#include <cstdint>
#include <math.h>

#define BSZ   8192
#define IND   1024
#define OUTD  1024
#define NSPLIT 4
#define NCHUNK 512

// ---- scratch (static device globals; no dynamic allocation) ----
__device__ float    g_u  [(size_t)BSZ * OUTD];           // 32 MB
__device__ float    g_yn [(size_t)BSZ * OUTD];           // 32 MB
__device__ float    g_P  [NCHUNK * OUTD];
__device__ float    g_m  [OUTD];
__device__ float    g_rate[OUTD];
__device__ float    g_S  [(size_t)NSPLIT * OUTD * IND];  // 16 MB
// GEMM1 operands: bf16 hi/lo (K-major)
__device__ uint16_t g_xh [(size_t)BSZ * IND];
__device__ uint16_t g_xl [(size_t)BSZ * IND];
__device__ uint16_t g_Wh [(size_t)OUTD * IND];
__device__ uint16_t g_Wl [(size_t)OUTD * IND];
// GEMM2 operands: f16 (x^T single, yn^T hi/lo)
__device__ uint16_t g_xTh [(size_t)IND * BSZ];
__device__ uint16_t g_ynTh[(size_t)OUTD * BSZ];
__device__ uint16_t g_ynTl[(size_t)OUTD * BSZ];

// ============================================================
// helpers
// ============================================================
__device__ __forceinline__ uint32_t bf16x2_rn(float hi, float lo) {
    uint32_t r;
    asm("cvt.rn.bf16x2.f32 %0, %1, %2;" : "=r"(r) : "f"(hi), "f"(lo));
    return r;
}
__device__ __forceinline__ void mma_bf16_k16(float c[4], const uint32_t a[4],
                                             const uint32_t b[2])
{
    asm volatile(
        "mma.sync.aligned.m16n8k16.row.col.f32.bf16.bf16.f32 "
        "{%0,%1,%2,%3}, {%4,%5,%6,%7}, {%8,%9}, {%0,%1,%2,%3};\n"
        : "+f"(c[0]), "+f"(c[1]), "+f"(c[2]), "+f"(c[3])
        : "r"(a[0]), "r"(a[1]), "r"(a[2]), "r"(a[3]),
          "r"(b[0]), "r"(b[1]));
}
__device__ __forceinline__ void mma_f16_k16(float c[4], const uint32_t a[4],
                                            const uint32_t b[2])
{
    asm volatile(
        "mma.sync.aligned.m16n8k16.row.col.f32.f16.f16.f32 "
        "{%0,%1,%2,%3}, {%4,%5,%6,%7}, {%8,%9}, {%0,%1,%2,%3};\n"
        : "+f"(c[0]), "+f"(c[1]), "+f"(c[2]), "+f"(c[3])
        : "r"(a[0]), "r"(a[1]), "r"(a[2]), "r"(a[3]),
          "r"(b[0]), "r"(b[1]));
}
__device__ __forceinline__ void ldsm_x4(uint32_t r[4], uint32_t addr) {
    asm volatile("ldmatrix.sync.aligned.m8n8.x4.shared.b16 {%0,%1,%2,%3}, [%4];"
        : "=r"(r[0]), "=r"(r[1]), "=r"(r[2]), "=r"(r[3]) : "r"(addr));
}
#define CP_ASYNC16(saddr, gptr) \
    asm volatile("cp.async.cg.shared.global [%0], [%1], 16;" \
        :: "r"(saddr), "l"(gptr))
// .noinc: arrive WITHOUT bumping expected-count (barrier inited to NTHREADS).
#define CP_MBAR_ARRIVE(mbar) \
    asm volatile("cp.async.mbarrier.arrive.noinc.shared::cta.b64 [%0];" \
        :: "r"((uint32_t)(mbar)) : "memory")
#define MBARRIER_INIT(mbar, cnt) \
    asm volatile("mbarrier.init.shared.b64 [%0], %1;" \
        :: "r"((uint32_t)(mbar)), "r"((uint32_t)(cnt)) : "memory")
#define MBARRIER_ARRIVE(mbar) \
    asm volatile("mbarrier.arrive.shared::cta.b64 _, [%0];" \
        :: "r"((uint32_t)(mbar)) : "memory")
#define MBARRIER_WAIT_PARITY(mbar, parity) do {                                   \
    uint32_t _m = (uint32_t)(mbar); uint32_t _p = (uint32_t)(parity);             \
    uint32_t _done;                                                               \
    asm volatile("{\n\t.reg .pred p;\n\t"                                         \
        "mbarrier.try_wait.parity.acquire.cta.shared::cta.b64 p, [%1], %2;\n\t"   \
        "selp.b32 %0, 1, 0, p;\n\t}" : "=r"(_done) : "r"(_m), "r"(_p) : "memory");\
    if (!_done) {                                                                 \
        asm volatile("{\n\t.reg .pred P1;\n\t"                                    \
            "WL_%=:\n\t"                                                          \
            "mbarrier.try_wait.parity.acquire.cta.shared::cta.b64 P1, [%0], %1, 0x989680;\n\t" \
            "@P1 bra.uni WD_%=;\n\t"                                              \
            "bra.uni WL_%=;\n\t"                                                  \
            "WD_%=:\n\t}" :: "r"(_m), "r"(_p) : "memory");                        \
    }                                                                             \
} while (0)

// Common geometry
#define BK      32
#define BM      256
#define BN      128
#define STRIDE  40
#define NSTAGE  3
#define NTHREADS 512

// ---- 3-pass (bf16) stage layout ----
#define SM_AH   0
#define SM_AL   (BM * STRIDE * 2)                          // 20480
#define SM_BH   (2 * BM * STRIDE * 2)                      // 40960
#define SM_BL   (2 * BM * STRIDE * 2 + BN * STRIDE * 2)    // 51200
#define STAGE_B (2 * BM * STRIDE * 2 + 2 * BN * STRIDE * 2) // 61440
#define SM_BARS (NSTAGE * STAGE_B)                         // 184320
#define SMEM_BYTES (SM_BARS + 64)

// ---- 2-pass (f16) stage layout: Ah, Al, Bh only ----
#define P2_AH    0
#define P2_AL    (BM * STRIDE * 2)                         // 20480
#define P2_BH    (2 * BM * STRIDE * 2)                     // 40960
#define STAGE2_B (2 * BM * STRIDE * 2 + BN * STRIDE * 2)   // 51200
#define SM2_BARS (NSTAGE * STAGE2_B)                       // 153600
#define SMEM2_BYTES (SM2_BARS + 64)

// ============================================================
// fill helpers
// ============================================================
__device__ __forceinline__ void fill_stage3(
    uint32_t sbase, int t,
    const uint16_t* __restrict__ Ah, const uint16_t* __restrict__ Al, int lda,
    const uint16_t* __restrict__ Bh, const uint16_t* __restrict__ Bl, int ldb,
    int m0, int n0, int ks0)
{
#pragma unroll
    for (int i = 0; i < 2; ++i) {
        const int c   = t + 512 * i;
        const int row = c >> 2;
        const int c16 = c & 3;
        const size_t go = (size_t)(m0 + row) * lda + ks0 + c16 * 8;
        const uint32_t so = (uint32_t)((row * STRIDE + c16 * 8) * 2);
        CP_ASYNC16(sbase + SM_AH + so, Ah + go);
        CP_ASYNC16(sbase + SM_AL + so, Al + go);
    }
    {
        const int row = t >> 2;
        const int c16 = t & 3;
        const size_t go = (size_t)(n0 + row) * ldb + ks0 + c16 * 8;
        const uint32_t so = (uint32_t)((row * STRIDE + c16 * 8) * 2);
        CP_ASYNC16(sbase + SM_BH + so, Bh + go);
        CP_ASYNC16(sbase + SM_BL + so, Bl + go);
    }
}

__device__ __forceinline__ void fill_stage2(
    uint32_t sbase, int t,
    const uint16_t* __restrict__ Ah, const uint16_t* __restrict__ Al, int lda,
    const uint16_t* __restrict__ Bh, int ldb,
    int m0, int n0, int ks0)
{
#pragma unroll
    for (int i = 0; i < 2; ++i) {
        const int c   = t + 512 * i;
        const int row = c >> 2;
        const int c16 = c & 3;
        const size_t go = (size_t)(m0 + row) * lda + ks0 + c16 * 8;
        const uint32_t so = (uint32_t)((row * STRIDE + c16 * 8) * 2);
        CP_ASYNC16(sbase + P2_AH + so, Ah + go);
        CP_ASYNC16(sbase + P2_AL + so, Al + go);
    }
    {
        const int row = t >> 2;
        const int c16 = t & 3;
        const size_t go = (size_t)(n0 + row) * ldb + ks0 + c16 * 8;
        const uint32_t so = (uint32_t)((row * STRIDE + c16 * 8) * 2);
        CP_ASYNC16(sbase + P2_BH + so, Bh + go);
    }
}

// ============================================================
// GEMM1: bf16x3 mma.sync with mbarrier full/empty ring (unchanged from R11).
// CTA 256x128, 512 thr / 16 warps (4M x 4N), warp tile 64x32.
// ============================================================
__global__ __launch_bounds__(NTHREADS, 1) void gemm_bf16v5_kernel(
    const uint16_t* __restrict__ Ah, const uint16_t* __restrict__ Al, int lda,
    const uint16_t* __restrict__ Bh, const uint16_t* __restrict__ Bl, int ldb,
    int kzstep, float* __restrict__ dstBase, int ldd, size_t zstride,
    const float* __restrict__ bias, int nstages)
{
    extern __shared__ uint16_t sm[];
    const uint32_t sbase0 = (uint32_t)__cvta_generic_to_shared(sm);
    const uint32_t barF = sbase0 + SM_BARS;
    const uint32_t barE = sbase0 + SM_BARS + 24;

    const int t     = threadIdx.x;
    const int lane  = t & 31;
    const int warp  = t >> 5;
    const int warpM = warp & 3;
    const int warpN = warp >> 2;
    const int m0    = blockIdx.y * BM;
    const int n0    = blockIdx.x * BN;
    const int kbase = blockIdx.z * kzstep;
    float* dst = dstBase + (size_t)blockIdx.z * zstride;

    const int gr   = lane >> 2;
    const int la15 = lane & 15;
    const int lhi  = lane >> 4;

    uint32_t aoff[4], boff[2];
#pragma unroll
    for (int mt = 0; mt < 4; ++mt)
        aoff[mt] = (uint32_t)(((warpM * 64 + mt * 16 + la15) * STRIDE
                               + lhi * 8) * 2);
#pragma unroll
    for (int p = 0; p < 2; ++p)
        boff[p] = (uint32_t)(((warpN * 32 + p * 16 + lhi * 8 + (lane & 7))
                               * STRIDE + ((lane >> 3) & 1) * 8) * 2);

    if (t == 0) {
#pragma unroll
        for (int j = 0; j < NSTAGE; ++j) {
            MBARRIER_INIT(barF + j * 8, NTHREADS);
            MBARRIER_INIT(barE + j * 8, NTHREADS);
        }
    }
    __syncthreads();

    float c[4][4][4];
#pragma unroll
    for (int mt = 0; mt < 4; ++mt)
#pragma unroll
        for (int nt = 0; nt < 4; ++nt)
#pragma unroll
            for (int e = 0; e < 4; ++e) c[mt][nt][e] = 0.f;

    fill_stage3(sbase0, t, Ah, Al, lda, Bh, Bl, ldb, m0, n0, kbase);
    CP_MBAR_ARRIVE(barF);

    int fs = 1, pslot = 1, pph = 0;
    int cslot = 0, cph = 0;

    for (int s = 0; s < nstages; ++s) {
        if (fs < nstages) {
            if (fs >= NSTAGE)
                MBARRIER_WAIT_PARITY(barE + pslot * 8, pph ^ 1);
            fill_stage3(sbase0 + pslot * STAGE_B, t, Ah, Al, lda, Bh, Bl, ldb,
                        m0, n0, kbase + fs * BK);
            CP_MBAR_ARRIVE(barF + pslot * 8);
            ++fs;
            if (++pslot == NSTAGE) { pslot = 0; pph ^= 1; }
        }

        MBARRIER_WAIT_PARITY(barF + cslot * 8, cph);
        const uint32_t sb  = sbase0 + cslot * STAGE_B;
        const uint32_t sAh = sb + SM_AH;
        const uint32_t sAl = sb + SM_AL;
        const uint32_t sBh = sb + SM_BH;
        const uint32_t sBl = sb + SM_BL;

#pragma unroll
        for (int ks = 0; ks < 2; ++ks) {
            const uint32_t ko = (uint32_t)(ks * 32);
            uint32_t ah[4][4], bb[4][2], t4[4];

#pragma unroll
            for (int mt = 0; mt < 4; ++mt)
                ldsm_x4(ah[mt], sAh + aoff[mt] + ko);
#pragma unroll
            for (int p = 0; p < 2; ++p) {
                ldsm_x4(t4, sBh + boff[p] + ko);
                bb[2*p][0] = t4[0]; bb[2*p][1] = t4[1];
                bb[2*p+1][0] = t4[2]; bb[2*p+1][1] = t4[3];
            }
#pragma unroll
            for (int mt = 0; mt < 4; ++mt)
#pragma unroll
                for (int nt = 0; nt < 4; ++nt)
                    mma_bf16_k16(c[mt][nt], ah[mt], bb[nt]);
            {
                uint32_t bl[4][2];
#pragma unroll
                for (int p = 0; p < 2; ++p) {
                    ldsm_x4(t4, sBl + boff[p] + ko);
                    bl[2*p][0] = t4[0]; bl[2*p][1] = t4[1];
                    bl[2*p+1][0] = t4[2]; bl[2*p+1][1] = t4[3];
                }
#pragma unroll
                for (int mt = 0; mt < 4; ++mt)
#pragma unroll
                    for (int nt = 0; nt < 4; ++nt)
                        mma_bf16_k16(c[mt][nt], ah[mt], bl[nt]);
            }
            {
                uint32_t al[4][4];
#pragma unroll
                for (int mt = 0; mt < 4; ++mt)
                    ldsm_x4(al[mt], sAl + aoff[mt] + ko);
                if (ks == 1)
                    MBARRIER_ARRIVE(barE + cslot * 8);
#pragma unroll
                for (int mt = 0; mt < 4; ++mt)
#pragma unroll
                    for (int nt = 0; nt < 4; ++nt)
                        mma_bf16_k16(c[mt][nt], al[mt], bb[nt]);
            }
        }
        if (++cslot == NSTAGE) { cslot = 0; cph ^= 1; }
    }

#pragma unroll
    for (int mt = 0; mt < 4; ++mt) {
        const int r = m0 + warpM * 64 + mt * 16 + gr;
#pragma unroll
        for (int nt = 0; nt < 4; ++nt) {
            const int cc = n0 + warpN * 32 + nt * 8 + (lane & 3) * 2;
            float2 v0 = make_float2(c[mt][nt][0], c[mt][nt][1]);
            float2 v1 = make_float2(c[mt][nt][2], c[mt][nt][3]);
            if (bias) {
                const float b0 = __ldg(&bias[cc]);
                const float b1 = __ldg(&bias[cc + 1]);
                v0.x += b0; v0.y += b1;
                v1.x += b0; v1.y += b1;
            }
            *reinterpret_cast<float2*>(&dst[(size_t)r * ldd + cc])       = v0;
            *reinterpret_cast<float2*>(&dst[(size_t)(r + 8) * ldd + cc]) = v1;
        }
    }
}

// ============================================================
// GEMM2: f16 2-pass (A = yn^T hi/lo f16, B = x^T f16 single).
// D += (Ahi + Alo) * B; dropped term = A * (x f16-rounding) ~ 2^-12 rel.
// Same ring structure; 3 smem buffers per stage.
// ============================================================
__global__ __launch_bounds__(NTHREADS, 1) void gemm_f16_2p_kernel(
    const uint16_t* __restrict__ Ah, const uint16_t* __restrict__ Al, int lda,
    const uint16_t* __restrict__ Bh, int ldb,
    int kzstep, float* __restrict__ dstBase, int ldd, size_t zstride,
    int nstages)
{
    extern __shared__ uint16_t sm[];
    const uint32_t sbase0 = (uint32_t)__cvta_generic_to_shared(sm);
    const uint32_t barF = sbase0 + SM2_BARS;
    const uint32_t barE = sbase0 + SM2_BARS + 24;

    const int t     = threadIdx.x;
    const int lane  = t & 31;
    const int warp  = t >> 5;
    const int warpM = warp & 3;
    const int warpN = warp >> 2;
    const int m0    = blockIdx.y * BM;
    const int n0    = blockIdx.x * BN;
    const int kbase = blockIdx.z * kzstep;
    float* dst = dstBase + (size_t)blockIdx.z * zstride;

    const int gr   = lane >> 2;
    const int la15 = lane & 15;
    const int lhi  = lane >> 4;

    uint32_t aoff[4], boff[2];
#pragma unroll
    for (int mt = 0; mt < 4; ++mt)
        aoff[mt] = (uint32_t)(((warpM * 64 + mt * 16 + la15) * STRIDE
                               + lhi * 8) * 2);
#pragma unroll
    for (int p = 0; p < 2; ++p)
        boff[p] = (uint32_t)(((warpN * 32 + p * 16 + lhi * 8 + (lane & 7))
                               * STRIDE + ((lane >> 3) & 1) * 8) * 2);

    if (t == 0) {
#pragma unroll
        for (int j = 0; j < NSTAGE; ++j) {
            MBARRIER_INIT(barF + j * 8, NTHREADS);
            MBARRIER_INIT(barE + j * 8, NTHREADS);
        }
    }
    __syncthreads();

    float c[4][4][4];
#pragma unroll
    for (int mt = 0; mt < 4; ++mt)
#pragma unroll
        for (int nt = 0; nt < 4; ++nt)
#pragma unroll
            for (int e = 0; e < 4; ++e) c[mt][nt][e] = 0.f;

    fill_stage2(sbase0, t, Ah, Al, lda, Bh, ldb, m0, n0, kbase);
    CP_MBAR_ARRIVE(barF);

    int fs = 1, pslot = 1, pph = 0;
    int cslot = 0, cph = 0;

    for (int s = 0; s < nstages; ++s) {
        if (fs < nstages) {
            if (fs >= NSTAGE)
                MBARRIER_WAIT_PARITY(barE + pslot * 8, pph ^ 1);
            fill_stage2(sbase0 + pslot * STAGE2_B, t, Ah, Al, lda, Bh, ldb,
                        m0, n0, kbase + fs * BK);
            CP_MBAR_ARRIVE(barF + pslot * 8);
            ++fs;
            if (++pslot == NSTAGE) { pslot = 0; pph ^= 1; }
        }

        MBARRIER_WAIT_PARITY(barF + cslot * 8, cph);
        const uint32_t sb  = sbase0 + cslot * STAGE2_B;
        const uint32_t sAh = sb + P2_AH;
        const uint32_t sAl = sb + P2_AL;
        const uint32_t sBh = sb + P2_BH;

#pragma unroll
        for (int ks = 0; ks < 2; ++ks) {
            const uint32_t ko = (uint32_t)(ks * 32);
            uint32_t ah[4][4], bb[4][2], t4[4];

#pragma unroll
            for (int mt = 0; mt < 4; ++mt)
                ldsm_x4(ah[mt], sAh + aoff[mt] + ko);
#pragma unroll
            for (int p = 0; p < 2; ++p) {
                ldsm_x4(t4, sBh + boff[p] + ko);
                bb[2*p][0] = t4[0]; bb[2*p][1] = t4[1];
                bb[2*p+1][0] = t4[2]; bb[2*p+1][1] = t4[3];
            }
            // hi * B
#pragma unroll
            for (int mt = 0; mt < 4; ++mt)
#pragma unroll
                for (int nt = 0; nt < 4; ++nt)
                    mma_f16_k16(c[mt][nt], ah[mt], bb[nt]);
            // lo * B
            {
                uint32_t al[4][4];
#pragma unroll
                for (int mt = 0; mt < 4; ++mt)
                    ldsm_x4(al[mt], sAl + aoff[mt] + ko);
                if (ks == 1)
                    MBARRIER_ARRIVE(barE + cslot * 8);
#pragma unroll
                for (int mt = 0; mt < 4; ++mt)
#pragma unroll
                    for (int nt = 0; nt < 4; ++nt)
                        mma_f16_k16(c[mt][nt], al[mt], bb[nt]);
            }
        }
        if (++cslot == NSTAGE) { cslot = 0; cph ^= 1; }
    }

#pragma unroll
    for (int mt = 0; mt < 4; ++mt) {
        const int r = m0 + warpM * 64 + mt * 16 + gr;
#pragma unroll
        for (int nt = 0; nt < 4; ++nt) {
            const int cc = n0 + warpN * 32 + nt * 8 + (lane & 3) * 2;
            *reinterpret_cast<float2*>(&dst[(size_t)r * ldd + cc]) =
                make_float2(c[mt][nt][0], c[mt][nt][1]);
            *reinterpret_cast<float2*>(&dst[(size_t)(r + 8) * ldd + cc]) =
                make_float2(c[mt][nt][2], c[mt][nt][3]);
        }
    }
}

// ============================================================
// Elementwise split (bf16): v -> hi = trunc-bf16(v), lo = rn-bf16(v - hi)
// ============================================================
__global__ __launch_bounds__(256) void split_kernel(
    const float* __restrict__ src, uint16_t* __restrict__ dh,
    uint16_t* __restrict__ dl, int n4)
{
    const int i = blockIdx.x * 256 + threadIdx.x;
    if (i >= n4) return;
    float4 v = reinterpret_cast<const float4*>(src)[i];
    uint32_t x0 = __float_as_uint(v.x), x1 = __float_as_uint(v.y);
    uint32_t x2 = __float_as_uint(v.z), x3 = __float_as_uint(v.w);
    uint32_t h01 = __byte_perm(x0, x1, 0x7632);
    uint32_t h23 = __byte_perm(x2, x3, 0x7632);
    float l0 = v.x - __uint_as_float(x0 & 0xFFFF0000u);
    float l1 = v.y - __uint_as_float(x1 & 0xFFFF0000u);
    float l2 = v.z - __uint_as_float(x2 & 0xFFFF0000u);
    float l3 = v.w - __uint_as_float(x3 & 0xFFFF0000u);
    reinterpret_cast<uint2*>(dh)[i] = make_uint2(h01, h23);
    reinterpret_cast<uint2*>(dl)[i] =
        make_uint2(bf16x2_rn(l1, l0), bf16x2_rn(l3, l2));
}

// ============================================================
// Transpose + f16 (hi only): src fp32 [R][C] -> dst f16 [C][R]
// ============================================================
__global__ __launch_bounds__(256) void transpose_f16_kernel(
    const float* __restrict__ src, uint16_t* __restrict__ dh, int R, int C)
{
    __shared__ float tile[32][33];
    const int c0 = blockIdx.x * 32;
    const int r0 = blockIdx.y * 32;
    const int tx = threadIdx.x, ty = threadIdx.y;
#pragma unroll
    for (int i = 0; i < 4; ++i)
        tile[ty + i*8][tx] = src[(size_t)(r0 + ty + i*8) * C + c0 + tx];
    __syncthreads();
#pragma unroll
    for (int i = 0; i < 4; ++i) {
        __half h = __float2half_rn(tile[tx][ty + i*8]);
        dh[(size_t)(c0 + ty + i*8) * R + r0 + tx] = __half_as_ushort(h);
    }
}

// ============================================================
// Transpose + f16 split: src fp32 [R][C] -> hi/lo f16 [C][R]
// ============================================================
__global__ __launch_bounds__(256) void transpose_split_f16_kernel(
    const float* __restrict__ src, uint16_t* __restrict__ dh,
    uint16_t* __restrict__ dl, int R, int C)
{
    __shared__ float tile[32][33];
    const int c0 = blockIdx.x * 32;
    const int r0 = blockIdx.y * 32;
    const int tx = threadIdx.x, ty = threadIdx.y;
#pragma unroll
    for (int i = 0; i < 4; ++i)
        tile[ty + i*8][tx] = src[(size_t)(r0 + ty + i*8) * C + c0 + tx];
    __syncthreads();
#pragma unroll
    for (int i = 0; i < 4; ++i) {
        float v = tile[tx][ty + i*8];
        __half h = __float2half_rn(v);
        float lo = v - __half2float(h);
        __half l = __float2half_rn(lo);
        const size_t o = (size_t)(c0 + ty + i*8) * R + r0 + tx;
        dh[o] = __half_as_ushort(h);
        dl[o] = __half_as_ushort(l);
    }
}

// ============================================================
// Per-row softmax + negate-non-maximal
// ============================================================
__global__ __launch_bounds__(256) void softmax_neg_kernel()
{
    const int b = blockIdx.x;
    const int t = threadIdx.x;
    const unsigned full = 0xffffffffu;

    float4 v = reinterpret_cast<const float4*>(&g_u[(size_t)b * OUTD])[t];

    float mx = v.x; int ai = t*4;
    if (v.y > mx) { mx = v.y; ai = t*4+1; }
    if (v.z > mx) { mx = v.z; ai = t*4+2; }
    if (v.w > mx) { mx = v.w; ai = t*4+3; }

#pragma unroll
    for (int off = 16; off > 0; off >>= 1) {
        float omx = __shfl_down_sync(full, mx, off);
        int   oai = __shfl_down_sync(full, ai, off);
        if (omx > mx || (omx == mx && oai < ai)) { mx = omx; ai = oai; }
    }
    __shared__ float smx[8];
    __shared__ int   sai[8];
    __shared__ float ssum[8];
    const int warp = t >> 5, lane = t & 31;
    if (lane == 0) { smx[warp] = mx; sai[warp] = ai; }
    __syncthreads();
    if (t == 0) {
        for (int w = 1; w < 8; ++w)
            if (smx[w] > smx[0] || (smx[w] == smx[0] && sai[w] < sai[0])) {
                smx[0] = smx[w]; sai[0] = sai[w];
            }
    }
    __syncthreads();
    const float MX = smx[0];
    const int   AI = sai[0];

    float4 e;
    e.x = expf(v.x - MX); e.y = expf(v.y - MX);
    e.z = expf(v.z - MX); e.w = expf(v.w - MX);
    float s = e.x + e.y + e.z + e.w;
#pragma unroll
    for (int off = 16; off > 0; off >>= 1) s += __shfl_down_sync(full, s, off);
    if (lane == 0) ssum[warp] = s;
    __syncthreads();
    if (t == 0) {
        float tot = 0.f;
        for (int w = 0; w < 8; ++w) tot += ssum[w];
        ssum[0] = tot;
    }
    __syncthreads();
    const float inv = 1.f / ssum[0];

    float4 o;
    o.x = (t*4+0 == AI) ? e.x*inv : -e.x*inv;
    o.y = (t*4+1 == AI) ? e.y*inv : -e.y*inv;
    o.z = (t*4+2 == AI) ? e.z*inv : -e.z*inv;
    o.w = (t*4+3 == AI) ? e.w*inv : -e.w*inv;
    reinterpret_cast<float4*>(&g_yn[(size_t)b * OUTD])[t] = o;
}

// ============================================================
// rate[o] = 1e-3 * |1 - ||W[o,:]||_2|^0.5
// ============================================================
__global__ __launch_bounds__(256) void rate_kernel(const float* __restrict__ W)
{
    const int o = blockIdx.x;
    const int t = threadIdx.x;
    const unsigned full = 0xffffffffu;
    float4 w = reinterpret_cast<const float4*>(&W[(size_t)o * IND])[t];
    float s = w.x*w.x + w.y*w.y + w.z*w.z + w.w*w.w;
#pragma unroll
    for (int off = 16; off > 0; off >>= 1) s += __shfl_down_sync(full, s, off);
    __shared__ float ssum[8];
    const int warp = t >> 5, lane = t & 31;
    if (lane == 0) ssum[warp] = s;
    __syncthreads();
    if (t == 0) {
        float tot = 0.f;
        for (int w2 = 0; w2 < 8; ++w2) tot += ssum[w2];
        float norm = sqrtf(tot);
        g_rate[o] = 1e-3f * sqrtf(fabsf(1.f - norm));
    }
}

// ============================================================
// m[o] = mean_b(yn[b,o] * u[b,o])
// ============================================================
__global__ __launch_bounds__(256) void col_partial_kernel()
{
    const int o = blockIdx.x * 256 + threadIdx.x;
    const int c = blockIdx.y;
    const int r0 = c * (BSZ / NCHUNK);
    float acc = 0.f;
#pragma unroll
    for (int r = 0; r < BSZ / NCHUNK; ++r) {
        const size_t off = (size_t)(r0 + r) * OUTD + o;
        acc += g_yn[off] * g_u[off];
    }
    g_P[c * OUTD + o] = acc;
}

__global__ __launch_bounds__(256) void m_final_kernel()
{
    const int o = blockIdx.x * 256 + threadIdx.x;
    float acc = 0.f;
    for (int c = 0; c < NCHUNK; ++c) acc += g_P[c * OUTD + o];
    g_m[o] = acc * (1.f / (float)BSZ);
}

// ============================================================
// out[o,i] = rate[o] * (sum_s S[s][o,i]/B - m[o]*W[o,i])
// ============================================================
__global__ __launch_bounds__(256) void epilogue_kernel(
    const float* __restrict__ W, float* __restrict__ out)
{
    const int o = blockIdx.x;
    const int t = threadIdx.x;
    const float m = g_m[o];
    const float r = g_rate[o];
    float4 wv = reinterpret_cast<const float4*>(&W[(size_t)o * IND])[t];
    float4 s = make_float4(0.f, 0.f, 0.f, 0.f);
#pragma unroll
    for (int sp = 0; sp < NSPLIT; ++sp) {
        float4 p = reinterpret_cast<const float4*>(
            &g_S[(size_t)sp * OUTD * IND + (size_t)o * IND])[t];
        s.x += p.x; s.y += p.y; s.z += p.z; s.w += p.w;
    }
    const float invB = 1.f / (float)BSZ;
    float4 ov;
    ov.x = r * (s.x * invB - m * wv.x);
    ov.y = r * (s.y * invB - m * wv.y);
    ov.z = r * (s.z * invB - m * wv.z);
    ov.w = r * (s.w * invB - m * wv.w);
    reinterpret_cast<float4*>(&out[(size_t)o * IND])[t] = ov;
}

// ============================================================
extern "C" void kernel_launch(void* const* d_in, const int* in_sizes, int n_in,
                              void* d_out, int out_size)
{
    const float* x = (const float*)d_in[0];   // [8192, 1024]
    const float* W = (const float*)d_in[1];   // [1024, 1024]
    const float* b = (const float*)d_in[2];   // [1024]
    float* out = (float*)d_out;               // [1024, 1024]

    cudaFuncSetAttribute(gemm_bf16v5_kernel,
                         cudaFuncAttributeMaxDynamicSharedMemorySize, SMEM_BYTES);
    cudaFuncSetAttribute(gemm_f16_2p_kernel,
                         cudaFuncAttributeMaxDynamicSharedMemorySize, SMEM2_BYTES);

    float*    g_u_p;    cudaGetSymbolAddress((void**)&g_u_p,    g_u);
    float*    g_yn_p;   cudaGetSymbolAddress((void**)&g_yn_p,   g_yn);
    float*    g_S_p;    cudaGetSymbolAddress((void**)&g_S_p,    g_S);
    uint16_t* g_xh_p;   cudaGetSymbolAddress((void**)&g_xh_p,   g_xh);
    uint16_t* g_xl_p;   cudaGetSymbolAddress((void**)&g_xl_p,   g_xl);
    uint16_t* g_Wh_p;   cudaGetSymbolAddress((void**)&g_Wh_p,   g_Wh);
    uint16_t* g_Wl_p;   cudaGetSymbolAddress((void**)&g_Wl_p,   g_Wl);
    uint16_t* g_xTh_p;  cudaGetSymbolAddress((void**)&g_xTh_p,  g_xTh);
    uint16_t* g_ynTh_p; cudaGetSymbolAddress((void**)&g_ynTh_p, g_ynTh);
    uint16_t* g_ynTl_p; cudaGetSymbolAddress((void**)&g_ynTl_p, g_ynTl);

    // GEMM1 inputs: bf16 hi/lo K-major
    split_kernel<<<(BSZ*IND/4 + 255)/256, 256>>>(x, g_xh_p, g_xl_p, BSZ*IND/4);
    split_kernel<<<(OUTD*IND/4 + 255)/256, 256>>>(W, g_Wh_p, g_Wl_p, OUTD*IND/4);
    // GEMM2 B operand: x^T as single f16
    transpose_f16_kernel<<<dim3(IND/32, BSZ/32), dim3(32, 8)>>>(
        x, g_xTh_p, BSZ, IND);

    // u = x @ W^T + b  (bf16x3)
    gemm_bf16v5_kernel<<<dim3(OUTD/BN, BSZ/BM, 1), NTHREADS, SMEM_BYTES>>>(
        g_xh_p, g_xl_p, IND, g_Wh_p, g_Wl_p, IND,
        0, g_u_p, OUTD, 0, b, IND / BK);
    // yn = negate_non_maximal(softmax(u))
    softmax_neg_kernel<<<BSZ, 256>>>();
    // yn^T as f16 hi/lo
    transpose_split_f16_kernel<<<dim3(OUTD/32, BSZ/32), dim3(32, 8)>>>(
        g_yn_p, g_ynTh_p, g_ynTl_p, BSZ, OUTD);
    // per-row rate + m[o]
    rate_kernel<<<OUTD, 256>>>(W);
    col_partial_kernel<<<dim3(OUTD/256, NCHUNK), 256>>>();
    m_final_kernel<<<OUTD/256, 256>>>();
    // S[z] = yn^T @ x partials  (f16 2-pass, split-K = 4)
    gemm_f16_2p_kernel<<<dim3(IND/BN, OUTD/BM, NSPLIT), NTHREADS, SMEM2_BYTES>>>(
        g_ynTh_p, g_ynTl_p, BSZ, g_xTh_p, BSZ,
        BSZ/NSPLIT, g_S_p, IND, (size_t)OUTD * IND, (BSZ/NSPLIT) / BK);
    // out = rate * (sum S / B - m*W)
    epilogue_kernel<<<OUTD, 256>>>(W, out);
}